// round 11
// baseline (speedup 1.0000x reference)
#include <cuda_runtime.h>
#include <cuda_bf16.h>
#include <cstdint>

// Attention_18631568130094: B=4, Sq=2048, Sk=2048, D=1024
// out[b,q,k] = mask[b,k] ? (Q[b,q]·K[b,k])/(|Q[b,q]||K[b,k]|) : -1e9
// Normalization folded into the fp8 quantization: prep stores q/|q|, k/|k|
// as e4m3 (relative error of fp8 is scale-invariant), so the GEMM accumulator
// IS the score and the epilogue is just a mask select.

#define B_  4
#define SQ  2048
#define SK  2048
#define DD  1024
#define NEGV -1000000000.0f

// ---------------- device scratch (no cudaMalloc allowed) -------------------
__device__ uint8_t g_q8[(size_t)B_ * SQ * DD];
__device__ uint8_t g_k8[(size_t)B_ * SK * DD];

// ---------------- helpers --------------------------------------------------
__device__ __forceinline__ uint32_t smem_u32(const void* p) {
    uint32_t a;
    asm("{ .reg .u64 t; cvta.to.shared.u64 t, %1; cvt.u32.u64 %0, t; }"
        : "=r"(a) : "l"(p));
    return a;
}
__device__ __forceinline__ void cp_async16(uint32_t s, const void* g) {
    asm volatile("cp.async.cg.shared.global [%0], [%1], 16;" :: "r"(s), "l"(g));
}
#define CP_COMMIT() asm volatile("cp.async.commit_group;" ::: "memory")
#define CP_WAIT(n)  asm volatile("cp.async.wait_group %0;" :: "n"(n) : "memory")

#define LDSM_X4(r0, r1, r2, r3, addr) \
    asm volatile("ldmatrix.sync.aligned.m8n8.x4.shared.b16 {%0,%1,%2,%3}, [%4];" \
        : "=r"(r0), "=r"(r1), "=r"(r2), "=r"(r3) : "r"(addr))

// fp8 e4m3 MMA: m16n8k32, fp32 accumulate.
#define MMA16832(d, a, bfr) \
    asm volatile("mma.sync.aligned.m16n8k32.row.col.f32.e4m3.e4m3.f32 " \
        "{%0,%1,%2,%3}, {%4,%5,%6,%7}, {%8,%9}, {%0,%1,%2,%3};" \
        : "+f"((d)[0]), "+f"((d)[1]), "+f"((d)[2]), "+f"((d)[3]) \
        : "r"((a)[0]), "r"((a)[1]), "r"((a)[2]), "r"((a)[3]), \
          "r"((bfr)[0]), "r"((bfr)[1]))

// pack 4 floats -> 4 e4m3 bytes (x at byte0 .. w at byte3)
__device__ __forceinline__ uint32_t pack_e4m3x4(float x, float y, float z, float w) {
    uint16_t h0, h1;
    asm("cvt.rn.satfinite.e4m3x2.f32 %0, %1, %2;" : "=h"(h0) : "f"(y), "f"(x));
    asm("cvt.rn.satfinite.e4m3x2.f32 %0, %1, %2;" : "=h"(h1) : "f"(w), "f"(z));
    uint32_t r;
    asm("mov.b32 %0, {%1, %2};" : "=r"(r) : "h"(h0), "h"(h1));
    return r;
}

// ---------------------------------------------------------------------------
// Kernel 1: row L2 norm, then store row/|row| as e4m3. One block per row.
// ---------------------------------------------------------------------------
__global__ __launch_bounds__(256) void prep_kernel(const float* __restrict__ q,
                                                   const float* __restrict__ k) {
    int row = blockIdx.x;
    const float* src;
    uint8_t* dst8;
    if (row < B_ * SQ) {
        src = q + (size_t)row * DD;
        dst8 = g_q8 + (size_t)row * DD;
    } else {
        int r = row - B_ * SQ;
        src = k + (size_t)r * DD;
        dst8 = g_k8 + (size_t)r * DD;
    }
    float4 v = ((const float4*)src)[threadIdx.x];  // 256*4 = 1024 exactly

    float s = v.x * v.x + v.y * v.y + v.z * v.z + v.w * v.w;
    #pragma unroll
    for (int off = 16; off > 0; off >>= 1)
        s += __shfl_xor_sync(0xFFFFFFFFu, s, off);

    __shared__ float red[8];
    __shared__ float s_inv;
    if ((threadIdx.x & 31) == 0) red[threadIdx.x >> 5] = s;
    __syncthreads();
    if (threadIdx.x == 0) {
        float t = 0.0f;
        #pragma unroll
        for (int i = 0; i < 8; i++) t += red[i];
        s_inv = 1.0f / fmaxf(sqrtf(t), 1e-8f);
    }
    __syncthreads();
    const float inv = s_inv;

    ((uint32_t*)dst8)[threadIdx.x] =
        pack_e4m3x4(v.x * inv, v.y * inv, v.z * inv, v.w * inv);
}

// ---------------------------------------------------------------------------
// Kernel 2: fp8 mma.sync GEMM on pre-normalized operands. CTA tile 128x128,
// BK=128 (fp8), 3-stage cp.async. 8 warps, warp tile 32x64, m16n8k32.
// Epilogue: mask select only (scores already cosine-normalized).
// SMEM stage: A 16KB + B 16KB = 32KB; rows are 128B, xor-swizzled by (row&7).
// ---------------------------------------------------------------------------
#define STAGES 3
#define NK 8                   // 1024 / 128
#define STAGE_BYTES 32768
#define SMEM_TOTAL (STAGES * STAGE_BYTES)

__global__ __launch_bounds__(256, 2) void gemm_mma_kernel(const int* __restrict__ mask,
                                                          float* __restrict__ out) {
    extern __shared__ char smem[];
    const int tid = threadIdx.x;
    const int b = blockIdx.z;
    const int bm = blockIdx.y * 128;
    const int bn = blockIdx.x * 128;

    __shared__ float s_mk[128];     // 0.0 = masked, 1.0 = keep
    if (tid < 128) {
        s_mk[tid] = mask[b * SK + bn + tid] ? 1.0f : 0.0f;
    }

    const uint8_t* Qb = g_q8 + ((size_t)b * SQ + bm) * DD;
    const uint8_t* Kb = g_k8 + ((size_t)b * SK + bn) * DD;

    // load mapping: thread t covers row t/2, chunks (t%2)*4 .. +3 (16B chunks)
    const int lr = tid >> 1;
    const int lc0 = (tid & 1) * 4;
    const uint32_t sb = smem_u32(smem);

    #define LOAD_TILE(slot, it) do {                                           \
        uint32_t sA = sb + (slot) * STAGE_BYTES;                               \
        uint32_t sB = sA + 16384;                                              \
        const uint8_t* gA = Qb + (size_t)lr * DD + (it) * 128 + lc0 * 16;      \
        const uint8_t* gB = Kb + (size_t)lr * DD + (it) * 128 + lc0 * 16;      \
        _Pragma("unroll")                                                      \
        for (int i = 0; i < 4; i++) {                                          \
            int c = lc0 + i;                                                   \
            uint32_t off = lr * 128 + ((c ^ (lr & 7)) * 16);                   \
            cp_async16(sA + off, gA + i * 16);                                 \
            cp_async16(sB + off, gB + i * 16);                                 \
        }                                                                      \
    } while (0)

    float acc[2][8][4];
    #pragma unroll
    for (int mf = 0; mf < 2; mf++)
        #pragma unroll
        for (int nf = 0; nf < 8; nf++)
            #pragma unroll
            for (int r = 0; r < 4; r++) acc[mf][nf][r] = 0.0f;

    const int w = tid >> 5, l = tid & 31;
    const int wm = (w & 3) * 32;     // warp m offset
    const int wn = (w >> 2) * 64;    // warp n offset

    LOAD_TILE(0, 0);
    CP_COMMIT();
    LOAD_TILE(1, 1);
    CP_COMMIT();

    uint32_t af[2][2][4];
    uint32_t bfr[2][8][2];

    // fragment fetch for k-subtile kk (one k32 step = 32B) into buffer p
    #define LOAD_FRAGS(p, sA, sB, kk) do {                                     \
        const int ch = (kk) * 2 + (l >> 4);                                    \
        _Pragma("unroll")                                                      \
        for (int mf = 0; mf < 2; mf++) {                                       \
            int row = wm + mf * 16 + (l & 15);                                 \
            uint32_t off = row * 128 + ((ch ^ (row & 7)) * 16);                \
            LDSM_X4(af[p][mf][0], af[p][mf][1], af[p][mf][2], af[p][mf][3],    \
                    (sA) + off);                                               \
        }                                                                      \
        _Pragma("unroll")                                                      \
        for (int nb = 0; nb < 4; nb++) {                                       \
            int row = wn + nb * 16 + (l & 15);                                 \
            uint32_t off = row * 128 + ((ch ^ (row & 7)) * 16);                \
            uint32_t r0, r1, r2, r3;                                           \
            LDSM_X4(r0, r1, r2, r3, (sB) + off);                               \
            bfr[p][2 * nb][0] = r0;     bfr[p][2 * nb][1] = r2;                \
            bfr[p][2 * nb + 1][0] = r1; bfr[p][2 * nb + 1][1] = r3;            \
        }                                                                      \
    } while (0)

    for (int it = 0; it < NK; it++) {
        CP_WAIT(1);
        __syncthreads();
        if (it + 2 < NK) LOAD_TILE((it + 2) % STAGES, it + 2);
        CP_COMMIT();

        uint32_t sA = sb + (it % STAGES) * STAGE_BYTES;
        uint32_t sB = sA + 16384;

        LOAD_FRAGS(0, sA, sB, 0);
        #pragma unroll
        for (int kk = 0; kk < 4; kk++) {
            const int cur = kk & 1;
            if (kk < 3) LOAD_FRAGS(cur ^ 1, sA, sB, kk + 1);
            #pragma unroll
            for (int mf = 0; mf < 2; mf++)
                #pragma unroll
                for (int nf = 0; nf < 8; nf++)
                    MMA16832(acc[mf][nf], af[cur][mf], bfr[cur][nf]);
        }
    }

    // ---- epilogue: mask select only (scores already normalized) ----
    // hoist this thread's 16 mask predicates out of smem once
    float mk0[8], mk1[8];
    #pragma unroll
    for (int nf = 0; nf < 8; nf++) {
        const int nl = wn + nf * 8 + (l & 3) * 2;
        mk0[nf] = s_mk[nl];
        mk1[nf] = s_mk[nl + 1];
    }

    #pragma unroll
    for (int mf = 0; mf < 2; mf++) {
        #pragma unroll
        for (int half = 0; half < 2; half++) {
            const int m = bm + wm + mf * 16 + (l >> 2) + half * 8;
            float* orow = out + ((size_t)b * SQ + m) * SK + bn;
            #pragma unroll
            for (int nf = 0; nf < 8; nf++) {
                const int nl = wn + nf * 8 + (l & 3) * 2;
                float2 o;
                o.x = (mk0[nf] == 0.0f) ? NEGV : acc[mf][nf][half * 2 + 0];
                o.y = (mk1[nf] == 0.0f) ? NEGV : acc[mf][nf][half * 2 + 1];
                *(float2*)(orow + nl) = o;
            }
        }
    }
}

// ---------------------------------------------------------------------------
extern "C" void kernel_launch(void* const* d_in, const int* in_sizes, int n_in,
                              void* d_out, int out_size) {
    const float* q = (const float*)d_in[0];
    const float* k = (const float*)d_in[1];
    const int* mask = (const int*)d_in[2];
    float* out = (float*)d_out;

    cudaFuncSetAttribute(gemm_mma_kernel,
                         cudaFuncAttributeMaxDynamicSharedMemorySize, SMEM_TOTAL);

    prep_kernel<<<B_ * SQ + B_ * SK, 256>>>(q, k);

    dim3 grid(SK / 128, SQ / 128, B_);
    gemm_mma_kernel<<<grid, 256, SMEM_TOTAL>>>(mask, out);
}

// round 12
// speedup vs baseline: 1.0407x; 1.0407x over previous
#include <cuda_runtime.h>
#include <cuda_bf16.h>
#include <cstdint>

// Attention_18631568130094: B=4, Sq=2048, Sk=2048, D=1024
// out[b,q,k] = mask[b,k] ? (Q[b,q]·K[b,k])/(|Q[b,q]||K[b,k]|) : -1e9
// Normalization folded into fp8 quantization: prep stores q/|q|, k/|k| as
// e4m3 (fp8 relative error is scale-invariant), so the GEMM accumulator IS
// the score and the epilogue is a mask select.

#define B_  4
#define SQ  2048
#define SK  2048
#define DD  1024
#define NEGV -1000000000.0f

// ---------------- device scratch (no cudaMalloc allowed) -------------------
__device__ uint8_t g_q8[(size_t)B_ * SQ * DD];
__device__ uint8_t g_k8[(size_t)B_ * SK * DD];

// ---------------- helpers --------------------------------------------------
__device__ __forceinline__ uint32_t smem_u32(const void* p) {
    uint32_t a;
    asm("{ .reg .u64 t; cvta.to.shared.u64 t, %1; cvt.u32.u64 %0, t; }"
        : "=r"(a) : "l"(p));
    return a;
}
__device__ __forceinline__ void cp_async16(uint32_t s, const void* g) {
    asm volatile("cp.async.cg.shared.global [%0], [%1], 16;" :: "r"(s), "l"(g));
}
#define CP_COMMIT() asm volatile("cp.async.commit_group;" ::: "memory")
#define CP_WAIT(n)  asm volatile("cp.async.wait_group %0;" :: "n"(n) : "memory")

#define LDSM_X4(r0, r1, r2, r3, addr) \
    asm volatile("ldmatrix.sync.aligned.m8n8.x4.shared.b16 {%0,%1,%2,%3}, [%4];" \
        : "=r"(r0), "=r"(r1), "=r"(r2), "=r"(r3) : "r"(addr))

// fp8 e4m3 MMA: m16n8k32, fp32 accumulate.
#define MMA16832(d, a, bfr) \
    asm volatile("mma.sync.aligned.m16n8k32.row.col.f32.e4m3.e4m3.f32 " \
        "{%0,%1,%2,%3}, {%4,%5,%6,%7}, {%8,%9}, {%0,%1,%2,%3};" \
        : "+f"((d)[0]), "+f"((d)[1]), "+f"((d)[2]), "+f"((d)[3]) \
        : "r"((a)[0]), "r"((a)[1]), "r"((a)[2]), "r"((a)[3]), \
          "r"((bfr)[0]), "r"((bfr)[1]))

// pack 4 floats -> 4 e4m3 bytes (x at byte0 .. w at byte3)
__device__ __forceinline__ uint32_t pack_e4m3x4(float x, float y, float z, float w) {
    uint16_t h0, h1;
    asm("cvt.rn.satfinite.e4m3x2.f32 %0, %1, %2;" : "=h"(h0) : "f"(y), "f"(x));
    asm("cvt.rn.satfinite.e4m3x2.f32 %0, %1, %2;" : "=h"(h1) : "f"(w), "f"(z));
    uint32_t r;
    asm("mov.b32 %0, {%1, %2};" : "=r"(r) : "h"(h0), "h"(h1));
    return r;
}

// ---------------------------------------------------------------------------
// Kernel 1: warp-per-row prep. Row (1024 fp32) lives in 32 regs/lane; warp
// shfl-reduce for the norm; normalize + e4m3-pack from registers. No smem,
// no block barriers. 8 rows per 256-thread CTA -> 2048 CTAs.
// ---------------------------------------------------------------------------
__global__ __launch_bounds__(256) void prep_kernel(const float* __restrict__ q,
                                                   const float* __restrict__ k) {
    const int row = blockIdx.x * 8 + (threadIdx.x >> 5);
    const int lane = threadIdx.x & 31;
    const float* src;
    uint8_t* dst8;
    if (row < B_ * SQ) {
        src = q + (size_t)row * DD;
        dst8 = g_q8 + (size_t)row * DD;
    } else {
        int r = row - B_ * SQ;
        src = k + (size_t)r * DD;
        dst8 = g_k8 + (size_t)r * DD;
    }

    const float4* s4 = (const float4*)src;
    float4 v[8];
    #pragma unroll
    for (int i = 0; i < 8; i++) v[i] = s4[lane + i * 32];

    float s = 0.0f;
    #pragma unroll
    for (int i = 0; i < 8; i++)
        s += v[i].x * v[i].x + v[i].y * v[i].y + v[i].z * v[i].z + v[i].w * v[i].w;
    #pragma unroll
    for (int off = 16; off > 0; off >>= 1)
        s += __shfl_xor_sync(0xFFFFFFFFu, s, off);

    const float inv = 1.0f / fmaxf(sqrtf(s), 1e-8f);

    uint32_t* d32 = (uint32_t*)dst8;
    #pragma unroll
    for (int i = 0; i < 8; i++)
        d32[lane + i * 32] =
            pack_e4m3x4(v[i].x * inv, v[i].y * inv, v[i].z * inv, v[i].w * inv);
}

// ---------------------------------------------------------------------------
// Kernel 2: fp8 mma.sync GEMM on pre-normalized operands. CTA tile 128x128,
// BK=128 (fp8), 3-stage cp.async. 8 warps, warp tile 32x64, m16n8k32.
// First LDSM burst issued before the next-tile prefetch so MMAs start early.
// Epilogue: mask select only. SMEM stage: A 16KB + B 16KB; 128B rows,
// xor-swizzled by (row&7).
// ---------------------------------------------------------------------------
#define STAGES 3
#define NK 8                   // 1024 / 128
#define STAGE_BYTES 32768
#define SMEM_TOTAL (STAGES * STAGE_BYTES)

__global__ __launch_bounds__(256, 2) void gemm_mma_kernel(const int* __restrict__ mask,
                                                          float* __restrict__ out) {
    extern __shared__ char smem[];
    const int tid = threadIdx.x;
    const int b = blockIdx.z;
    const int bm = blockIdx.y * 128;
    const int bn = blockIdx.x * 128;

    __shared__ float s_mk[128];     // 0.0 = masked, 1.0 = keep
    if (tid < 128) {
        s_mk[tid] = mask[b * SK + bn + tid] ? 1.0f : 0.0f;
    }

    const uint8_t* Qb = g_q8 + ((size_t)b * SQ + bm) * DD;
    const uint8_t* Kb = g_k8 + ((size_t)b * SK + bn) * DD;

    // load mapping: thread t covers row t/2, chunks (t%2)*4 .. +3 (16B chunks)
    const int lr = tid >> 1;
    const int lc0 = (tid & 1) * 4;
    const uint32_t sb = smem_u32(smem);

    #define LOAD_TILE(slot, it) do {                                           \
        uint32_t sA_ = sb + (slot) * STAGE_BYTES;                              \
        uint32_t sB_ = sA_ + 16384;                                            \
        const uint8_t* gA = Qb + (size_t)lr * DD + (it) * 128 + lc0 * 16;      \
        const uint8_t* gB = Kb + (size_t)lr * DD + (it) * 128 + lc0 * 16;      \
        _Pragma("unroll")                                                      \
        for (int i = 0; i < 4; i++) {                                          \
            int c = lc0 + i;                                                   \
            uint32_t off = lr * 128 + ((c ^ (lr & 7)) * 16);                   \
            cp_async16(sA_ + off, gA + i * 16);                                \
            cp_async16(sB_ + off, gB + i * 16);                                \
        }                                                                      \
    } while (0)

    float acc[2][8][4];
    #pragma unroll
    for (int mf = 0; mf < 2; mf++)
        #pragma unroll
        for (int nf = 0; nf < 8; nf++)
            #pragma unroll
            for (int r = 0; r < 4; r++) acc[mf][nf][r] = 0.0f;

    const int w = tid >> 5, l = tid & 31;
    const int wm = (w & 3) * 32;     // warp m offset
    const int wn = (w >> 2) * 64;    // warp n offset

    LOAD_TILE(0, 0);
    CP_COMMIT();
    LOAD_TILE(1, 1);
    CP_COMMIT();

    uint32_t af[2][2][4];
    uint32_t bfr[2][8][2];

    // fragment fetch for k-subtile kk (one k32 step = 32B) into buffer p
    #define LOAD_FRAGS(p, sA, sB, kk) do {                                     \
        const int ch = (kk) * 2 + (l >> 4);                                    \
        _Pragma("unroll")                                                      \
        for (int mf = 0; mf < 2; mf++) {                                       \
            int row = wm + mf * 16 + (l & 15);                                 \
            uint32_t off = row * 128 + ((ch ^ (row & 7)) * 16);                \
            LDSM_X4(af[p][mf][0], af[p][mf][1], af[p][mf][2], af[p][mf][3],    \
                    (sA) + off);                                               \
        }                                                                      \
        _Pragma("unroll")                                                      \
        for (int nb = 0; nb < 4; nb++) {                                       \
            int row = wn + nb * 16 + (l & 15);                                 \
            uint32_t off = row * 128 + ((ch ^ (row & 7)) * 16);                \
            uint32_t r0, r1, r2, r3;                                           \
            LDSM_X4(r0, r1, r2, r3, (sB) + off);                               \
            bfr[p][2 * nb][0] = r0;     bfr[p][2 * nb][1] = r2;                \
            bfr[p][2 * nb + 1][0] = r1; bfr[p][2 * nb + 1][1] = r3;            \
        }                                                                      \
    } while (0)

    for (int it = 0; it < NK; it++) {
        CP_WAIT(1);
        __syncthreads();

        uint32_t sA = sb + (it % STAGES) * STAGE_BYTES;
        uint32_t sB = sA + 16384;

        // first fragment burst before the prefetch so MMAs can start ASAP
        LOAD_FRAGS(0, sA, sB, 0);

        if (it + 2 < NK) LOAD_TILE((it + 2) % STAGES, it + 2);
        CP_COMMIT();

        #pragma unroll
        for (int kk = 0; kk < 4; kk++) {
            const int cur = kk & 1;
            if (kk < 3) LOAD_FRAGS(cur ^ 1, sA, sB, kk + 1);
            #pragma unroll
            for (int mf = 0; mf < 2; mf++)
                #pragma unroll
                for (int nf = 0; nf < 8; nf++)
                    MMA16832(acc[mf][nf], af[cur][mf], bfr[cur][nf]);
        }
    }

    // ---- epilogue: mask select only (scores already normalized) ----
    float mk0[8], mk1[8];
    #pragma unroll
    for (int nf = 0; nf < 8; nf++) {
        const int nl = wn + nf * 8 + (l & 3) * 2;
        mk0[nf] = s_mk[nl];
        mk1[nf] = s_mk[nl + 1];
    }

    #pragma unroll
    for (int mf = 0; mf < 2; mf++) {
        #pragma unroll
        for (int half = 0; half < 2; half++) {
            const int m = bm + wm + mf * 16 + (l >> 2) + half * 8;
            float* orow = out + ((size_t)b * SQ + m) * SK + bn;
            #pragma unroll
            for (int nf = 0; nf < 8; nf++) {
                const int nl = wn + nf * 8 + (l & 3) * 2;
                float2 o;
                o.x = (mk0[nf] == 0.0f) ? NEGV : acc[mf][nf][half * 2 + 0];
                o.y = (mk1[nf] == 0.0f) ? NEGV : acc[mf][nf][half * 2 + 1];
                *(float2*)(orow + nl) = o;
            }
        }
    }
}

// ---------------------------------------------------------------------------
extern "C" void kernel_launch(void* const* d_in, const int* in_sizes, int n_in,
                              void* d_out, int out_size) {
    const float* q = (const float*)d_in[0];
    const float* k = (const float*)d_in[1];
    const int* mask = (const int*)d_in[2];
    float* out = (float*)d_out;

    cudaFuncSetAttribute(gemm_mma_kernel,
                         cudaFuncAttributeMaxDynamicSharedMemorySize, SMEM_TOTAL);

    prep_kernel<<<(B_ * SQ + B_ * SK) / 8, 256>>>(q, k);

    dim3 grid(SK / 128, SQ / 128, B_);
    gemm_mma_kernel<<<grid, 256, SMEM_TOTAL>>>(mask, out);
}

// round 13
// speedup vs baseline: 1.0458x; 1.0050x over previous
#include <cuda_runtime.h>
#include <cuda_bf16.h>
#include <cstdint>

// Attention_18631568130094: B=4, Sq=2048, Sk=2048, D=1024
// out[b,q,k] = mask[b,k] ? (Q[b,q]·K[b,k])/(|Q[b,q]||K[b,k]|) : -1e9
// Normalization folded into fp8 quantization: prep stores q/|q|, k/|k| as
// e4m3 (fp8 relative error is scale-invariant), so the GEMM accumulator IS
// the score and the epilogue is a mask select.

#define B_  4
#define SQ  2048
#define SK  2048
#define DD  1024
#define NEGV -1000000000.0f

// ---------------- device scratch (no cudaMalloc allowed) -------------------
__device__ uint8_t g_q8[(size_t)B_ * SQ * DD];
__device__ uint8_t g_k8[(size_t)B_ * SK * DD];

// ---------------- helpers --------------------------------------------------
__device__ __forceinline__ uint32_t smem_u32(const void* p) {
    uint32_t a;
    asm("{ .reg .u64 t; cvta.to.shared.u64 t, %1; cvt.u32.u64 %0, t; }"
        : "=r"(a) : "l"(p));
    return a;
}
__device__ __forceinline__ void cp_async16(uint32_t s, const void* g) {
    asm volatile("cp.async.cg.shared.global [%0], [%1], 16;" :: "r"(s), "l"(g));
}
#define CP_COMMIT() asm volatile("cp.async.commit_group;" ::: "memory")
#define CP_WAIT(n)  asm volatile("cp.async.wait_group %0;" :: "n"(n) : "memory")

#define LDSM_X4(r0, r1, r2, r3, addr) \
    asm volatile("ldmatrix.sync.aligned.m8n8.x4.shared.b16 {%0,%1,%2,%3}, [%4];" \
        : "=r"(r0), "=r"(r1), "=r"(r2), "=r"(r3) : "r"(addr))

// fp8 e4m3 MMA: m16n8k32, fp32 accumulate.
#define MMA16832(d, a, bfr) \
    asm volatile("mma.sync.aligned.m16n8k32.row.col.f32.e4m3.e4m3.f32 " \
        "{%0,%1,%2,%3}, {%4,%5,%6,%7}, {%8,%9}, {%0,%1,%2,%3};" \
        : "+f"((d)[0]), "+f"((d)[1]), "+f"((d)[2]), "+f"((d)[3]) \
        : "r"((a)[0]), "r"((a)[1]), "r"((a)[2]), "r"((a)[3]), \
          "r"((bfr)[0]), "r"((bfr)[1]))

// pack 4 floats -> 4 e4m3 bytes (x at byte0 .. w at byte3)
__device__ __forceinline__ uint32_t pack_e4m3x4(float x, float y, float z, float w) {
    uint16_t h0, h1;
    asm("cvt.rn.satfinite.e4m3x2.f32 %0, %1, %2;" : "=h"(h0) : "f"(y), "f"(x));
    asm("cvt.rn.satfinite.e4m3x2.f32 %0, %1, %2;" : "=h"(h1) : "f"(w), "f"(z));
    uint32_t r;
    asm("mov.b32 %0, {%1, %2};" : "=r"(r) : "h"(h0), "h"(h1));
    return r;
}

// ---------------------------------------------------------------------------
// Kernel 1: warp-per-row prep. Row (1024 fp32) lives in 32 regs/lane; warp
// shfl-reduce for the norm; normalize + e4m3-pack from registers. No smem,
// no block barriers. 8 rows per 256-thread CTA -> 2048 CTAs.
// ---------------------------------------------------------------------------
__global__ __launch_bounds__(256) void prep_kernel(const float* __restrict__ q,
                                                   const float* __restrict__ k) {
    const int row = blockIdx.x * 8 + (threadIdx.x >> 5);
    const int lane = threadIdx.x & 31;
    const float* src;
    uint8_t* dst8;
    if (row < B_ * SQ) {
        src = q + (size_t)row * DD;
        dst8 = g_q8 + (size_t)row * DD;
    } else {
        int r = row - B_ * SQ;
        src = k + (size_t)r * DD;
        dst8 = g_k8 + (size_t)r * DD;
    }

    const float4* s4 = (const float4*)src;
    float4 v[8];
    #pragma unroll
    for (int i = 0; i < 8; i++) v[i] = s4[lane + i * 32];

    float s = 0.0f;
    #pragma unroll
    for (int i = 0; i < 8; i++)
        s += v[i].x * v[i].x + v[i].y * v[i].y + v[i].z * v[i].z + v[i].w * v[i].w;
    #pragma unroll
    for (int off = 16; off > 0; off >>= 1)
        s += __shfl_xor_sync(0xFFFFFFFFu, s, off);

    const float inv = 1.0f / fmaxf(sqrtf(s), 1e-8f);

    uint32_t* d32 = (uint32_t*)dst8;
    #pragma unroll
    for (int i = 0; i < 8; i++)
        d32[lane + i * 32] =
            pack_e4m3x4(v[i].x * inv, v[i].y * inv, v[i].z * inv, v[i].w * inv);
}

// ---------------------------------------------------------------------------
// Kernel 2: fp8 mma.sync GEMM on pre-normalized operands. CTA tile 128x128,
// BK=128 (fp8), 3-stage cp.async. 8 warps, warp tile 32x64, m16n8k32.
// Iteration order (R6-proven): barrier -> prefetch cp.async -> fragments.
// Epilogue: mask select only. SMEM stage: A 16KB + B 16KB; 128B rows,
// xor-swizzled by (row&7).
// ---------------------------------------------------------------------------
#define STAGES 3
#define NK 8                   // 1024 / 128
#define STAGE_BYTES 32768
#define SMEM_TOTAL (STAGES * STAGE_BYTES)

__global__ __launch_bounds__(256, 2) void gemm_mma_kernel(const int* __restrict__ mask,
                                                          float* __restrict__ out) {
    extern __shared__ char smem[];
    const int tid = threadIdx.x;
    const int b = blockIdx.z;
    const int bm = blockIdx.y * 128;
    const int bn = blockIdx.x * 128;

    __shared__ float s_mk[128];     // 0.0 = masked, 1.0 = keep
    if (tid < 128) {
        s_mk[tid] = mask[b * SK + bn + tid] ? 1.0f : 0.0f;
    }

    const uint8_t* Qb = g_q8 + ((size_t)b * SQ + bm) * DD;
    const uint8_t* Kb = g_k8 + ((size_t)b * SK + bn) * DD;

    // load mapping: thread t covers row t/2, chunks (t%2)*4 .. +3 (16B chunks)
    const int lr = tid >> 1;
    const int lc0 = (tid & 1) * 4;
    const uint32_t sb = smem_u32(smem);

    #define LOAD_TILE(slot, it) do {                                           \
        uint32_t sA_ = sb + (slot) * STAGE_BYTES;                              \
        uint32_t sB_ = sA_ + 16384;                                            \
        const uint8_t* gA = Qb + (size_t)lr * DD + (it) * 128 + lc0 * 16;      \
        const uint8_t* gB = Kb + (size_t)lr * DD + (it) * 128 + lc0 * 16;      \
        _Pragma("unroll")                                                      \
        for (int i = 0; i < 4; i++) {                                          \
            int c = lc0 + i;                                                   \
            uint32_t off = lr * 128 + ((c ^ (lr & 7)) * 16);                   \
            cp_async16(sA_ + off, gA + i * 16);                                \
            cp_async16(sB_ + off, gB + i * 16);                                \
        }                                                                      \
    } while (0)

    float acc[2][8][4];
    #pragma unroll
    for (int mf = 0; mf < 2; mf++)
        #pragma unroll
        for (int nf = 0; nf < 8; nf++)
            #pragma unroll
            for (int r = 0; r < 4; r++) acc[mf][nf][r] = 0.0f;

    const int w = tid >> 5, l = tid & 31;
    const int wm = (w & 3) * 32;     // warp m offset
    const int wn = (w >> 2) * 64;    // warp n offset

    LOAD_TILE(0, 0);
    CP_COMMIT();
    LOAD_TILE(1, 1);
    CP_COMMIT();

    uint32_t af[2][2][4];
    uint32_t bfr[2][8][2];

    // fragment fetch for k-subtile kk (one k32 step = 32B) into buffer p
    #define LOAD_FRAGS(p, sA, sB, kk) do {                                     \
        const int ch = (kk) * 2 + (l >> 4);                                    \
        _Pragma("unroll")                                                      \
        for (int mf = 0; mf < 2; mf++) {                                       \
            int row = wm + mf * 16 + (l & 15);                                 \
            uint32_t off = row * 128 + ((ch ^ (row & 7)) * 16);                \
            LDSM_X4(af[p][mf][0], af[p][mf][1], af[p][mf][2], af[p][mf][3],    \
                    (sA) + off);                                               \
        }                                                                      \
        _Pragma("unroll")                                                      \
        for (int nb = 0; nb < 4; nb++) {                                       \
            int row = wn + nb * 16 + (l & 15);                                 \
            uint32_t off = row * 128 + ((ch ^ (row & 7)) * 16);                \
            uint32_t r0, r1, r2, r3;                                           \
            LDSM_X4(r0, r1, r2, r3, (sB) + off);                               \
            bfr[p][2 * nb][0] = r0;     bfr[p][2 * nb][1] = r2;                \
            bfr[p][2 * nb + 1][0] = r1; bfr[p][2 * nb + 1][1] = r3;            \
        }                                                                      \
    } while (0)

    for (int it = 0; it < NK; it++) {
        CP_WAIT(1);
        __syncthreads();
        if (it + 2 < NK) LOAD_TILE((it + 2) % STAGES, it + 2);
        CP_COMMIT();

        uint32_t sA = sb + (it % STAGES) * STAGE_BYTES;
        uint32_t sB = sA + 16384;

        LOAD_FRAGS(0, sA, sB, 0);
        #pragma unroll
        for (int kk = 0; kk < 4; kk++) {
            const int cur = kk & 1;
            if (kk < 3) LOAD_FRAGS(cur ^ 1, sA, sB, kk + 1);
            #pragma unroll
            for (int mf = 0; mf < 2; mf++)
                #pragma unroll
                for (int nf = 0; nf < 8; nf++)
                    MMA16832(acc[mf][nf], af[cur][mf], bfr[cur][nf]);
        }
    }

    // ---- epilogue: mask select only (scores already normalized) ----
    float mk0[8], mk1[8];
    #pragma unroll
    for (int nf = 0; nf < 8; nf++) {
        const int nl = wn + nf * 8 + (l & 3) * 2;
        mk0[nf] = s_mk[nl];
        mk1[nf] = s_mk[nl + 1];
    }

    #pragma unroll
    for (int mf = 0; mf < 2; mf++) {
        #pragma unroll
        for (int half = 0; half < 2; half++) {
            const int m = bm + wm + mf * 16 + (l >> 2) + half * 8;
            float* orow = out + ((size_t)b * SQ + m) * SK + bn;
            #pragma unroll
            for (int nf = 0; nf < 8; nf++) {
                const int nl = wn + nf * 8 + (l & 3) * 2;
                float2 o;
                o.x = (mk0[nf] == 0.0f) ? NEGV : acc[mf][nf][half * 2 + 0];
                o.y = (mk1[nf] == 0.0f) ? NEGV : acc[mf][nf][half * 2 + 1];
                *(float2*)(orow + nl) = o;
            }
        }
    }
}

// ---------------------------------------------------------------------------
extern "C" void kernel_launch(void* const* d_in, const int* in_sizes, int n_in,
                              void* d_out, int out_size) {
    const float* q = (const float*)d_in[0];
    const float* k = (const float*)d_in[1];
    const int* mask = (const int*)d_in[2];
    float* out = (float*)d_out;

    cudaFuncSetAttribute(gemm_mma_kernel,
                         cudaFuncAttributeMaxDynamicSharedMemorySize, SMEM_TOTAL);

    prep_kernel<<<(B_ * SQ + B_ * SK) / 8, 256>>>(q, k);

    dim3 grid(SK / 128, SQ / 128, B_);
    gemm_mma_kernel<<<grid, 256, SMEM_TOTAL>>>(mask, out);
}